// round 1
// baseline (speedup 1.0000x reference)
#include <cuda_runtime.h>
#include <math.h>

// ---------------------------------------------------------------------------
// HFLongFormerSelfAttentionBlock: B=2, S0=2048, H=1024, NH=16, HD=64, W=128
// Key simplifications (proved against reference):
//  * padded rows (s>=2048) are discarded by [:, :s0] -> global-query branch dead
//  * global key/value = bk/bv per head (xp pad rows are zero)
//  * keys j in [2048,2303] always masked for kept queries -> window clamps to [0,2047]
// Pipeline: QKV gemms -> banded flash attention -> add+LN -> MLP1(gelu) -> MLP2(+res)
// ---------------------------------------------------------------------------

#define NEGF (-3.4028234663852886e38f)

// scratch (device globals; no allocation allowed)
__device__ float g_q[4194304];     // (B,NH,S0,HD)
__device__ float g_k[4194304];
__device__ float g_v[4194304];
__device__ float g_attn[4194304];  // (B*S0, H)
__device__ float g_y[4194304];     // LN output
__device__ float g_h[16777216];    // MLP hidden (4096,4096)

// ---------------------------------------------------------------------------
// Generic fp32 GEMM: C = epi(A[M,K] @ W[K,N] + bias)
// 128x128 tile, BK=8, 256 threads, 8x8 microtile, double-buffered smem.
// EPI 0: out=(acc+bias)*scale, remapped to (B,NH,S,HD) layout
// EPI 1: out=gelu_exact(acc+bias)
// EPI 2: out=acc+bias+res
// ---------------------------------------------------------------------------
template<int EPI>
__global__ __launch_bounds__(256)
void gemm_kernel(const float* __restrict__ A, const float* __restrict__ W,
                 const float* __restrict__ bias, const float* __restrict__ res,
                 float* __restrict__ C, int M, int N, int K, float scale)
{
    __shared__ float As[2][8][128];
    __shared__ float Bs[2][8][128];
    const int tid = threadIdx.x;
    const int tx = tid & 15, ty = tid >> 4;
    const int m0 = blockIdx.y * 128, n0 = blockIdx.x * 128;
    const int a_r = tid >> 1, a_c = (tid & 1) << 2;
    const int b_r = tid >> 5, b_c = (tid & 31) << 2;
    const float* Ap = A + (size_t)(m0 + a_r) * K + a_c;
    const float* Wp = W + (size_t)b_r * N + n0 + b_c;

    float acc[8][8];
#pragma unroll
    for (int i = 0; i < 8; i++)
#pragma unroll
        for (int j = 0; j < 8; j++) acc[i][j] = 0.f;

    float4 a4 = *(const float4*)Ap;
    float4 b4 = *(const float4*)Wp;
    As[0][a_c+0][a_r]=a4.x; As[0][a_c+1][a_r]=a4.y;
    As[0][a_c+2][a_r]=a4.z; As[0][a_c+3][a_r]=a4.w;
    *(float4*)&Bs[0][b_r][b_c] = b4;
    __syncthreads();

    const int nk = K >> 3;
    for (int kt = 0; kt < nk; kt++) {
        const int buf = kt & 1;
        float4 a4n, b4n;
        if (kt + 1 < nk) {
            a4n = *(const float4*)(Ap + (kt + 1) * 8);
            b4n = *(const float4*)(Wp + (size_t)(kt + 1) * 8 * N);
        }
#pragma unroll
        for (int kk = 0; kk < 8; kk++) {
            float4 a0 = *(const float4*)&As[buf][kk][ty << 2];
            float4 a1 = *(const float4*)&As[buf][kk][64 + (ty << 2)];
            float4 b0 = *(const float4*)&Bs[buf][kk][tx << 2];
            float4 b1 = *(const float4*)&Bs[buf][kk][64 + (tx << 2)];
            float av[8] = {a0.x,a0.y,a0.z,a0.w,a1.x,a1.y,a1.z,a1.w};
            float bw[8] = {b0.x,b0.y,b0.z,b0.w,b1.x,b1.y,b1.z,b1.w};
#pragma unroll
            for (int i = 0; i < 8; i++)
#pragma unroll
                for (int j = 0; j < 8; j++)
                    acc[i][j] = fmaf(av[i], bw[j], acc[i][j]);
        }
        if (kt + 1 < nk) {
            const int nb = buf ^ 1;
            As[nb][a_c+0][a_r]=a4n.x; As[nb][a_c+1][a_r]=a4n.y;
            As[nb][a_c+2][a_r]=a4n.z; As[nb][a_c+3][a_r]=a4n.w;
            *(float4*)&Bs[nb][b_r][b_c] = b4n;
        }
        __syncthreads();
    }

#pragma unroll
    for (int i = 0; i < 8; i++) {
        const int mrow = m0 + ((i < 4) ? ((ty << 2) + i) : (64 + (ty << 2) + i - 4));
#pragma unroll
        for (int jb = 0; jb < 2; jb++) {
            const int ncol = n0 + jb * 64 + (tx << 2);
            float4 bb = *(const float4*)&bias[ncol];
            float o0 = acc[i][jb*4+0] + bb.x;
            float o1 = acc[i][jb*4+1] + bb.y;
            float o2 = acc[i][jb*4+2] + bb.z;
            float o3 = acc[i][jb*4+3] + bb.w;
            float4 o;
            if (EPI == 0) {
                o.x = o0 * scale; o.y = o1 * scale; o.z = o2 * scale; o.w = o3 * scale;
                const int bi = mrow >> 11, ss = mrow & 2047;
                const int hh = ncol >> 6, dd = ncol & 63;
                *(float4*)&C[(((size_t)((bi * 16 + hh) * 2048 + ss)) << 6) + dd] = o;
            } else if (EPI == 1) {
                const float c_ = 0.70710678118654752f;
                o.x = 0.5f * o0 * (1.f + erff(o0 * c_));
                o.y = 0.5f * o1 * (1.f + erff(o1 * c_));
                o.z = 0.5f * o2 * (1.f + erff(o2 * c_));
                o.w = 0.5f * o3 * (1.f + erff(o3 * c_));
                *(float4*)&C[(size_t)mrow * N + ncol] = o;
            } else {
                float4 r4 = *(const float4*)&res[(size_t)mrow * N + ncol];
                o.x = o0 + r4.x; o.y = o1 + r4.y; o.z = o2 + r4.z; o.w = o3 + r4.w;
                *(float4*)&C[(size_t)mrow * N + ncol] = o;
            }
        }
    }
}

// ---------------------------------------------------------------------------
// Banded attention with online softmax + global-key epilogue.
// One block = (b, h, 64-query tile). Key chunks of 64 (all chunks are either
// fully inside [0,2048) or fully outside because tiles are 64-aligned).
// smem: Qs[d][r], Ks[d][c], Vs[j][d], Ps[r][65], rem[64]
// ---------------------------------------------------------------------------
__global__ __launch_bounds__(256)
void attn_kernel(const float* __restrict__ Q, const float* __restrict__ Kt,
                 const float* __restrict__ Vt, const int* __restrict__ mask,
                 const float* __restrict__ bk, const float* __restrict__ bv,
                 float* __restrict__ out)
{
    extern __shared__ float sm[];
    float* Qs = sm;                 // 64x64  [d][r]
    float* Ks = sm + 4096;          // 64x64  [d][c]
    float* Vs = sm + 8192;          // 64x64  [j][d]
    float* Ps = sm + 12288;         // 64x65  [r][c]
    float* rem = sm + 12288 + 64*65;

    const int qb = blockIdx.x, h = blockIdx.y, b = blockIdx.z;
    const int qstart = qb << 6;
    const int tid = threadIdx.x, tx = tid & 15, ty = tid >> 4;
    const size_t bh = (size_t)(b * 16 + h) * 2048 * 64;
    const float* Qb = Q + bh;
    const float* Kb = Kt + bh;
    const float* Vb = Vt + bh;
    const int r0 = ty << 2, c0 = tx << 2;

    // load Q tile transposed (d-major)
    for (int i = tid; i < 1024; i += 256) {
        int r = i & 63, d4 = (i >> 6) << 2;
        float4 q4 = *(const float4*)&Qb[((size_t)(qstart + r) << 6) + d4];
        Qs[(d4+0)*64+r]=q4.x; Qs[(d4+1)*64+r]=q4.y;
        Qs[(d4+2)*64+r]=q4.z; Qs[(d4+3)*64+r]=q4.w;
    }

    float O[4][4];
    float mrow[4], lrow[4];
#pragma unroll
    for (int i = 0; i < 4; i++) {
        mrow[i] = -INFINITY; lrow[i] = 0.f;
#pragma unroll
        for (int j = 0; j < 4; j++) O[i][j] = 0.f;
    }

    for (int ch = 0; ch < 5; ch++) {
        const int jbase = qstart - 128 + (ch << 6);
        if (jbase < 0 || jbase >= 2048) continue;
        __syncthreads();  // prior-iteration readers of Ks/Vs/Ps done (also covers Qs on 1st)
        for (int i = tid; i < 1024; i += 256) {
            int c = i & 63, d4 = (i >> 6) << 2;
            float4 k4 = *(const float4*)&Kb[((size_t)(jbase + c) << 6) + d4];
            Ks[(d4+0)*64+c]=k4.x; Ks[(d4+1)*64+c]=k4.y;
            Ks[(d4+2)*64+c]=k4.z; Ks[(d4+3)*64+c]=k4.w;
        }
        for (int i = tid; i < 1024; i += 256) {
            int j = i >> 4, d4 = (i & 15) << 2;
            *(float4*)&Vs[j * 64 + d4] = *(const float4*)&Vb[((size_t)(jbase + j) << 6) + d4];
        }
        if (tid < 64)
            rem[tid] = (mask[b * 2048 + jbase + tid] != 0) ? NEGF : 0.f;
        __syncthreads();

        // S = Q K^T  (64x64x64 mini-GEMM)
        float s[4][4];
#pragma unroll
        for (int i = 0; i < 4; i++)
#pragma unroll
            for (int j = 0; j < 4; j++) s[i][j] = 0.f;
#pragma unroll 8
        for (int d = 0; d < 64; d++) {
            float4 a = *(const float4*)&Qs[d * 64 + r0];
            float4 kk = *(const float4*)&Ks[d * 64 + c0];
            float av[4] = {a.x,a.y,a.z,a.w};
            float kv[4] = {kk.x,kk.y,kk.z,kk.w};
#pragma unroll
            for (int i = 0; i < 4; i++)
#pragma unroll
                for (int j = 0; j < 4; j++)
                    s[i][j] = fmaf(av[i], kv[j], s[i][j]);
        }

        // mask + online softmax update (row groups = 16 contiguous lanes)
#pragma unroll
        for (int i = 0; i < 4; i++) {
            float mx = -INFINITY;
#pragma unroll
            for (int j = 0; j < 4; j++) {
                int c = c0 + j, r = r0 + i;
                float sc = s[i][j] + rem[c];
                int dist = jbase + c - qstart - r;
                if (dist < -128 || dist > 128) sc = -INFINITY;
                s[i][j] = sc;
                mx = fmaxf(mx, sc);
            }
#pragma unroll
            for (int off = 8; off > 0; off >>= 1)
                mx = fmaxf(mx, __shfl_xor_sync(0xffffffffu, mx, off, 16));
            float mnew = fmaxf(mrow[i], mx);
            float corr = __expf(mrow[i] - mnew);
            mrow[i] = mnew;
            float ps = 0.f;
#pragma unroll
            for (int j = 0; j < 4; j++) {
                float p = __expf(s[i][j] - mnew);
                Ps[(r0 + i) * 65 + c0 + j] = p;
                ps += p;
            }
#pragma unroll
            for (int off = 8; off > 0; off >>= 1)
                ps += __shfl_xor_sync(0xffffffffu, ps, off, 16);
            lrow[i] = lrow[i] * corr + ps;
#pragma unroll
            for (int j = 0; j < 4; j++) O[i][j] *= corr;
        }
        __syncthreads();

        // O += P V
#pragma unroll 8
        for (int jj = 0; jj < 64; jj++) {
            float4 vv = *(const float4*)&Vs[jj * 64 + c0];
            float pv[4] = {vv.x, vv.y, vv.z, vv.w};
#pragma unroll
            for (int i = 0; i < 4; i++) {
                float p = Ps[(r0 + i) * 65 + jj];
#pragma unroll
                for (int j = 0; j < 4; j++)
                    O[i][j] = fmaf(p, pv[j], O[i][j]);
            }
        }
    }

    // global key (k=bk_head, v=bv_head, never masked)
    const float* bkh = bk + h * 64;
    const float* bvh = bv + h * 64;
    float gp[4] = {0.f, 0.f, 0.f, 0.f};
#pragma unroll
    for (int t = 0; t < 4; t++) {
        int d = c0 + t;
        float kbv = bkh[d];
#pragma unroll
        for (int i = 0; i < 4; i++)
            gp[i] += Qs[d * 64 + r0 + i] * kbv;
    }
#pragma unroll
    for (int i = 0; i < 4; i++) {
#pragma unroll
        for (int off = 8; off > 0; off >>= 1)
            gp[i] += __shfl_xor_sync(0xffffffffu, gp[i], off, 16);
        float g = gp[i];
        float mnew = fmaxf(mrow[i], g);
        float corr = __expf(mrow[i] - mnew);
        float eg = __expf(g - mnew);
        lrow[i] = lrow[i] * corr + eg;
        mrow[i] = mnew;
#pragma unroll
        for (int j = 0; j < 4; j++)
            O[i][j] = O[i][j] * corr + eg * bvh[c0 + j];
    }

    // finalize + masked-query zeroing; write (B*S0, H) layout
#pragma unroll
    for (int i = 0; i < 4; i++) {
        int srow = qstart + r0 + i;
        int mv = mask[b * 2048 + srow];
        float inv = (mv > 0) ? 0.f : (1.f / lrow[i]);
        float4 o;
        o.x = O[i][0]*inv; o.y = O[i][1]*inv; o.z = O[i][2]*inv; o.w = O[i][3]*inv;
        *(float4*)&out[(((size_t)(b * 2048 + srow)) << 10) + (h << 6) + c0] = o;
    }
}

// ---------------------------------------------------------------------------
// y = LN(x + attn) * gamma + beta   (one block per row of 1024)
// ---------------------------------------------------------------------------
__global__ __launch_bounds__(256)
void ln_kernel(const float* __restrict__ x, const float* __restrict__ attn,
               const float* __restrict__ gamma, const float* __restrict__ beta,
               float* __restrict__ y)
{
    __shared__ float red[8];
    __shared__ float stat;
    const int row = blockIdx.x, tid = threadIdx.x;
    const int lane = tid & 31, wid = tid >> 5;
    const float* xr = x + ((size_t)row << 10);
    const float* ar = attn + ((size_t)row << 10);
    float v[4];
#pragma unroll
    for (int i = 0; i < 4; i++) {
        int c = tid + (i << 8);
        v[i] = xr[c] + ar[c];
    }
    float s = v[0] + v[1] + v[2] + v[3];
#pragma unroll
    for (int off = 16; off > 0; off >>= 1) s += __shfl_xor_sync(~0u, s, off);
    if (lane == 0) red[wid] = s;
    __syncthreads();
    if (tid == 0) {
        float t = 0.f;
        for (int i = 0; i < 8; i++) t += red[i];
        stat = t * (1.f / 1024.f);
    }
    __syncthreads();
    const float mu = stat;
    float d2 = 0.f;
#pragma unroll
    for (int i = 0; i < 4; i++) { float d = v[i] - mu; d2 += d * d; }
#pragma unroll
    for (int off = 16; off > 0; off >>= 1) d2 += __shfl_xor_sync(~0u, d2, off);
    if (lane == 0) red[wid] = d2;
    __syncthreads();
    if (tid == 0) {
        float t = 0.f;
        for (int i = 0; i < 8; i++) t += red[i];
        stat = rsqrtf(t * (1.f / 1024.f) + 1e-5f);
    }
    __syncthreads();
    const float rs = stat;
    float* yr = y + ((size_t)row << 10);
#pragma unroll
    for (int i = 0; i < 4; i++) {
        int c = tid + (i << 8);
        yr[c] = (v[i] - mu) * rs * gamma[c] + beta[c];
    }
}

// ---------------------------------------------------------------------------
extern "C" void kernel_launch(void* const* d_in, const int* in_sizes, int n_in,
                              void* d_out, int out_size)
{
    const float* x    = (const float*)d_in[0];
    const int*   mask = (const int*)d_in[1];
    const float* wq   = (const float*)d_in[2];
    const float* bq   = (const float*)d_in[3];
    const float* wk   = (const float*)d_in[4];
    const float* bk   = (const float*)d_in[5];
    const float* wv   = (const float*)d_in[6];
    const float* bv   = (const float*)d_in[7];
    // d_in[8..13]: global-attention weights — dead code (row S-1 is discarded)
    const float* ln_g = (const float*)d_in[14];
    const float* ln_b = (const float*)d_in[15];
    const float* w1   = (const float*)d_in[16];
    const float* b1   = (const float*)d_in[17];
    const float* w2   = (const float*)d_in[18];
    const float* b2   = (const float*)d_in[19];

    float *q, *k, *v, *attn, *y, *hh;
    cudaGetSymbolAddress((void**)&q,    g_q);
    cudaGetSymbolAddress((void**)&k,    g_k);
    cudaGetSymbolAddress((void**)&v,    g_v);
    cudaGetSymbolAddress((void**)&attn, g_attn);
    cudaGetSymbolAddress((void**)&y,    g_y);
    cudaGetSymbolAddress((void**)&hh,   g_h);

    const int ATT_SMEM = (64*64*3 + 64*65 + 64) * 4;  // 66048 B
    cudaFuncSetAttribute(attn_kernel,
                         cudaFuncAttributeMaxDynamicSharedMemorySize, ATT_SMEM);

    dim3 blk(256);
    // QKV projections (q pre-scaled by 1/sqrt(HD), bias scaled too, per reference)
    gemm_kernel<0><<<dim3(8, 32), blk>>>(x, wq, bq, nullptr, q, 4096, 1024, 1024, 0.125f);
    gemm_kernel<0><<<dim3(8, 32), blk>>>(x, wk, bk, nullptr, k, 4096, 1024, 1024, 1.0f);
    gemm_kernel<0><<<dim3(8, 32), blk>>>(x, wv, bv, nullptr, v, 4096, 1024, 1024, 1.0f);
    // banded attention + global key
    attn_kernel<<<dim3(32, 16, 2), blk, ATT_SMEM>>>(q, k, v, mask, bk, bv, attn);
    // residual add + layernorm
    ln_kernel<<<4096, blk>>>(x, attn, ln_g, ln_b, y);
    // MLP
    gemm_kernel<1><<<dim3(32, 32), blk>>>(y, w1, b1, nullptr, hh, 4096, 4096, 1024, 1.0f);
    gemm_kernel<2><<<dim3(8, 32), blk>>>(hh, w2, b2, y, (float*)d_out, 4096, 1024, 4096, 1.0f);
}

// round 3
// speedup vs baseline: 1.7100x; 1.7100x over previous
#include <cuda_runtime.h>
#include <cuda_bf16.h>
#include <math.h>
#include <stdint.h>

// ---------------------------------------------------------------------------
// HFLongFormerSelfAttentionBlock on GB300 (sm_103a harness, base sm_103 PTX
// target -> tcgen05 unavailable; use portable mma.sync bf16 HMMA path).
// All GEMMs: split-precision bf16 (hi/lo) with fp32 accumulation:
//   x@w ~= hi@whi + hi@wlo + lo@whi
// ---------------------------------------------------------------------------

#define NEGF (-3.4028234663852886e38f)

// ---------------- scratch (device globals; no allocation allowed) ----------
__device__ float g_q[4194304];     // (B,NH,S0,HD)
__device__ float g_k[4194304];
__device__ float g_v[4194304];
__device__ float g_attn[4194304];  // (B*S0, H)
__device__ float g_y[4194304];     // LN output fp32
__device__ __nv_bfloat16 g_xhi[4194304], g_xlo[4194304];
__device__ __nv_bfloat16 g_yhi[4194304], g_ylo[4194304];
__device__ __nv_bfloat16 g_hhi[16777216], g_hlo[16777216];
__device__ __nv_bfloat16 g_wqt_hi[1048576], g_wqt_lo[1048576];
__device__ __nv_bfloat16 g_wkt_hi[1048576], g_wkt_lo[1048576];
__device__ __nv_bfloat16 g_wvt_hi[1048576], g_wvt_lo[1048576];
__device__ __nv_bfloat16 g_w1t_hi[4194304], g_w1t_lo[4194304];
__device__ __nv_bfloat16 g_w2t_hi[4194304], g_w2t_lo[4194304];

// ---------------- PTX helpers ----------------------------------------------
__device__ __forceinline__ uint32_t smem_u32(const void* p) {
    uint32_t a;
    asm("{ .reg .u64 t; cvta.to.shared.u64 t, %1; cvt.u32.u64 %0, t; }"
        : "=r"(a) : "l"(p));
    return a;
}
__device__ __forceinline__ void cp_async16(uint32_t saddr, const void* gptr) {
    asm volatile("cp.async.ca.shared.global [%0], [%1], 16;"
                 :: "r"(saddr), "l"(gptr));
}
__device__ __forceinline__ void cp_commit() {
    asm volatile("cp.async.commit_group;");
}
template<int N>
__device__ __forceinline__ void cp_wait() {
    asm volatile("cp.async.wait_group %0;" :: "n"(N));
}
__device__ __forceinline__ void ldsm_x4(uint32_t& r0, uint32_t& r1,
                                        uint32_t& r2, uint32_t& r3, uint32_t a) {
    asm volatile("ldmatrix.sync.aligned.m8n8.x4.shared.b16 {%0,%1,%2,%3}, [%4];"
                 : "=r"(r0), "=r"(r1), "=r"(r2), "=r"(r3) : "r"(a));
}
__device__ __forceinline__ void mma_bf16(float* c, const uint32_t* a,
                                         uint32_t b0, uint32_t b1) {
    asm volatile(
        "mma.sync.aligned.m16n8k16.row.col.f32.bf16.bf16.f32 "
        "{%0,%1,%2,%3}, {%4,%5,%6,%7}, {%8,%9}, {%0,%1,%2,%3};"
        : "+f"(c[0]), "+f"(c[1]), "+f"(c[2]), "+f"(c[3])
        : "r"(a[0]), "r"(a[1]), "r"(a[2]), "r"(a[3]), "r"(b0), "r"(b1));
}

// ---------------------------------------------------------------------------
// split: fp32 -> (hi, lo) bf16, elementwise (vectorized by 4)
// ---------------------------------------------------------------------------
__global__ __launch_bounds__(256)
void split_kernel(const float4* __restrict__ in, __nv_bfloat162* __restrict__ hi,
                  __nv_bfloat162* __restrict__ lo, int n4)
{
    int i = blockIdx.x * 256 + threadIdx.x;
    if (i >= n4) return;
    float4 v = in[i];
    __nv_bfloat16 h0 = __float2bfloat16(v.x), h1 = __float2bfloat16(v.y);
    __nv_bfloat16 h2 = __float2bfloat16(v.z), h3 = __float2bfloat16(v.w);
    hi[2*i]   = __halves2bfloat162(h0, h1);
    hi[2*i+1] = __halves2bfloat162(h2, h3);
    lo[2*i]   = __halves2bfloat162(__float2bfloat16(v.x - __bfloat162float(h0)),
                                   __float2bfloat16(v.y - __bfloat162float(h1)));
    lo[2*i+1] = __halves2bfloat162(__float2bfloat16(v.z - __bfloat162float(h2)),
                                   __float2bfloat16(v.w - __bfloat162float(h3)));
}

// ---------------------------------------------------------------------------
// transpose-split: W[K,N] fp32 -> Thi/Tlo[N,K] bf16 (32x32 smem tiles)
// ---------------------------------------------------------------------------
__global__ __launch_bounds__(256)
void tsplit_kernel(const float* __restrict__ W, __nv_bfloat16* __restrict__ Thi,
                   __nv_bfloat16* __restrict__ Tlo, int K, int N)
{
    __shared__ float ts[32][33];
    const int k0 = blockIdx.y << 5, n0 = blockIdx.x << 5;
    for (int i = threadIdx.x; i < 1024; i += 256) {
        int r = i >> 5, c = i & 31;
        ts[r][c] = W[(size_t)(k0 + r) * N + n0 + c];
    }
    __syncthreads();
    for (int i = threadIdx.x; i < 1024; i += 256) {
        int r = i >> 5, c = i & 31;   // r = n index, c = k index
        float v = ts[c][r];
        __nv_bfloat16 h = __float2bfloat16(v);
        size_t o = (size_t)(n0 + r) * K + k0 + c;
        Thi[o] = h;
        Tlo[o] = __float2bfloat16(v - __bfloat162float(h));
    }
}

// ---------------------------------------------------------------------------
// HMMA split-bf16 GEMM: out = epi(Ahi/lo[M,K] @ (Bhi/lo[N,K])^T + bias)
// CTA 128x128, BK=64, 256 threads (8 warps 2x4, warp tile 64x32),
// smem row stride 72 bf16 (conflict-free ldmatrix), cp.async double buffer.
// EPI 0: fp32*scale -> (B,NH,S,HD) remap (QKV)
// EPI 1: gelu -> bf16 hi/lo (MLP hidden)
// EPI 2: +bias+res -> fp32 (final output)
// ---------------------------------------------------------------------------
#define SA_STRIDE 72
#define TILE_B    18432   // 128*72*2 bytes per array
#define BUF_B     73728   // 4 arrays

template<int EPI>
__global__ __launch_bounds__(256)
void mma_gemm(const __nv_bfloat16* __restrict__ Ahi, const __nv_bfloat16* __restrict__ Alo,
              const __nv_bfloat16* __restrict__ Bhi, const __nv_bfloat16* __restrict__ Blo,
              const float* __restrict__ bias, const float* __restrict__ res,
              float* __restrict__ Cf, __nv_bfloat16* __restrict__ Chi,
              __nv_bfloat16* __restrict__ Clo,
              int M, int N, int K, float scale)
{
    extern __shared__ char smem[];
    const uint32_t sb = smem_u32(smem);
    const int tid = threadIdx.x, wid = tid >> 5, lane = tid & 31;
    const int m0 = blockIdx.y << 7, n0 = blockIdx.x << 7;
    const int wm = (wid >> 2) << 6;       // 0 or 64
    const int wn = (wid & 3) << 5;        // 0,32,64,96

    // ldmatrix lane addressing (element offsets)
    const int a_row = lane & 15, a_kof = (lane >> 4) << 3;
    const int b_row = ((lane >> 4) << 3) + (lane & 7), b_kof = ((lane >> 3) & 1) << 3;

    // global->smem copy mapping: row = tid>>1, 4 chunks of 8 bf16
    const int c_row = tid >> 1, c_col = (tid & 1) << 5;

    float acc[4][4][4];
#pragma unroll
    for (int mt = 0; mt < 4; mt++)
#pragma unroll
        for (int nt = 0; nt < 4; nt++)
#pragma unroll
            for (int r = 0; r < 4; r++) acc[mt][nt][r] = 0.f;

    const int nk = K >> 6;

    // ---- tile loader (cp.async) ----
    auto load_tile = [&](int buf, int kt) {
        const uint32_t sbase = sb + buf * BUF_B;
        const size_t gka = (size_t)(m0 + c_row) * K + ((size_t)kt << 6) + c_col;
        const size_t gkb = (size_t)(n0 + c_row) * K + ((size_t)kt << 6) + c_col;
        const uint32_t soff = (c_row * SA_STRIDE + c_col) * 2;
#pragma unroll
        for (int j = 0; j < 4; j++) {
            cp_async16(sbase + soff + j * 16,               Ahi + gka + j * 8);
            cp_async16(sbase + TILE_B   + soff + j * 16,    Alo + gka + j * 8);
            cp_async16(sbase + 2*TILE_B + soff + j * 16,    Bhi + gkb + j * 8);
            cp_async16(sbase + 3*TILE_B + soff + j * 16,    Blo + gkb + j * 8);
        }
        cp_commit();
    };

    load_tile(0, 0);

    for (int kt = 0; kt < nk; kt++) {
        const int buf = kt & 1;
        if (kt + 1 < nk) { load_tile(buf ^ 1, kt + 1); cp_wait<1>(); }
        else             { cp_wait<0>(); }
        __syncthreads();

        const uint32_t sAhi = sb + buf * BUF_B;
        const uint32_t sAlo = sAhi + TILE_B;
        const uint32_t sBhi = sAhi + 2 * TILE_B;
        const uint32_t sBlo = sAhi + 3 * TILE_B;

#pragma unroll
        for (int ks = 0; ks < 4; ks++) {
            const int k0 = ks << 4;
            uint32_t ah[4][4], al[4][4];
#pragma unroll
            for (int mt = 0; mt < 4; mt++) {
                const uint32_t off =
                    ((wm + (mt << 4) + a_row) * SA_STRIDE + k0 + a_kof) * 2;
                ldsm_x4(ah[mt][0], ah[mt][1], ah[mt][2], ah[mt][3], sAhi + off);
                ldsm_x4(al[mt][0], al[mt][1], al[mt][2], al[mt][3], sAlo + off);
            }
            uint32_t bh[4][2], bl[4][2];
#pragma unroll
            for (int nt2 = 0; nt2 < 2; nt2++) {
                const uint32_t off =
                    ((wn + (nt2 << 4) + b_row) * SA_STRIDE + k0 + b_kof) * 2;
                uint32_t r0, r1, r2, r3;
                ldsm_x4(r0, r1, r2, r3, sBhi + off);
                bh[nt2*2][0] = r0; bh[nt2*2][1] = r1;
                bh[nt2*2+1][0] = r2; bh[nt2*2+1][1] = r3;
                ldsm_x4(r0, r1, r2, r3, sBlo + off);
                bl[nt2*2][0] = r0; bl[nt2*2][1] = r1;
                bl[nt2*2+1][0] = r2; bl[nt2*2+1][1] = r3;
            }
#pragma unroll
            for (int mt = 0; mt < 4; mt++)
#pragma unroll
                for (int nt = 0; nt < 4; nt++) {
                    mma_bf16(acc[mt][nt], ah[mt], bh[nt][0], bh[nt][1]);
                    mma_bf16(acc[mt][nt], ah[mt], bl[nt][0], bl[nt][1]);
                    mma_bf16(acc[mt][nt], al[mt], bh[nt][0], bh[nt][1]);
                }
        }
        __syncthreads();
    }

    // ---- epilogue ----
    const int mrow_b = m0 + wm + (lane >> 2);
    const int ncol_b = n0 + wn + ((lane & 3) << 1);
#pragma unroll
    for (int mt = 0; mt < 4; mt++) {
#pragma unroll
        for (int half = 0; half < 2; half++) {
            const int m = mrow_b + (mt << 4) + (half << 3);
#pragma unroll
            for (int nt = 0; nt < 4; nt++) {
                const int ncol = ncol_b + (nt << 3);
                const float b0 = bias[ncol], b1 = bias[ncol + 1];
                float o0 = acc[mt][nt][half*2+0] + b0;
                float o1 = acc[mt][nt][half*2+1] + b1;
                if (EPI == 0) {
                    o0 *= scale; o1 *= scale;
                    const int bi = m >> 11, ss = m & 2047;
                    const int hh = ncol >> 6, dd = ncol & 63;
                    float2* p = (float2*)&Cf[(((size_t)((bi*16 + hh)*2048 + ss)) << 6) + dd];
                    *p = make_float2(o0, o1);
                } else if (EPI == 1) {
                    const float c_ = 0.70710678118654752f;
                    float g0 = 0.5f * o0 * (1.f + erff(o0 * c_));
                    float g1 = 0.5f * o1 * (1.f + erff(o1 * c_));
                    __nv_bfloat16 h0 = __float2bfloat16(g0);
                    __nv_bfloat16 h1 = __float2bfloat16(g1);
                    size_t o = (size_t)m * N + ncol;
                    *(__nv_bfloat162*)(Chi + o) = __halves2bfloat162(h0, h1);
                    *(__nv_bfloat162*)(Clo + o) =
                        __halves2bfloat162(__float2bfloat16(g0 - __bfloat162float(h0)),
                                           __float2bfloat16(g1 - __bfloat162float(h1)));
                } else {
                    const float2 r4 = *(const float2*)&res[(size_t)m * N + ncol];
                    *(float2*)&Cf[(size_t)m * N + ncol] =
                        make_float2(o0 + r4.x, o1 + r4.y);
                }
            }
        }
    }
}

// ---------------------------------------------------------------------------
// Banded attention with online softmax + global-key epilogue (R1, unchanged)
// ---------------------------------------------------------------------------
__global__ __launch_bounds__(256)
void attn_kernel(const float* __restrict__ Q, const float* __restrict__ Kt,
                 const float* __restrict__ Vt, const int* __restrict__ mask,
                 const float* __restrict__ bk, const float* __restrict__ bv,
                 float* __restrict__ out)
{
    extern __shared__ float sm[];
    float* Qs = sm;                 // 64x64  [d][r]
    float* Ks = sm + 4096;          // 64x64  [d][c]
    float* Vs = sm + 8192;          // 64x64  [j][d]
    float* Ps = sm + 12288;         // 64x65  [r][c]
    float* rem = sm + 12288 + 64*65;

    const int qb = blockIdx.x, h = blockIdx.y, b = blockIdx.z;
    const int qstart = qb << 6;
    const int tid = threadIdx.x, tx = tid & 15, ty = tid >> 4;
    const size_t bh = (size_t)(b * 16 + h) * 2048 * 64;
    const float* Qb = Q + bh;
    const float* Kb = Kt + bh;
    const float* Vb = Vt + bh;
    const int r0 = ty << 2, c0 = tx << 2;

    for (int i = tid; i < 1024; i += 256) {
        int r = i & 63, d4 = (i >> 6) << 2;
        float4 q4 = *(const float4*)&Qb[((size_t)(qstart + r) << 6) + d4];
        Qs[(d4+0)*64+r]=q4.x; Qs[(d4+1)*64+r]=q4.y;
        Qs[(d4+2)*64+r]=q4.z; Qs[(d4+3)*64+r]=q4.w;
    }

    float O[4][4];
    float mrow[4], lrow[4];
#pragma unroll
    for (int i = 0; i < 4; i++) {
        mrow[i] = -INFINITY; lrow[i] = 0.f;
#pragma unroll
        for (int j = 0; j < 4; j++) O[i][j] = 0.f;
    }

    for (int ch = 0; ch < 5; ch++) {
        const int jbase = qstart - 128 + (ch << 6);
        if (jbase < 0 || jbase >= 2048) continue;
        __syncthreads();
        for (int i = tid; i < 1024; i += 256) {
            int c = i & 63, d4 = (i >> 6) << 2;
            float4 k4 = *(const float4*)&Kb[((size_t)(jbase + c) << 6) + d4];
            Ks[(d4+0)*64+c]=k4.x; Ks[(d4+1)*64+c]=k4.y;
            Ks[(d4+2)*64+c]=k4.z; Ks[(d4+3)*64+c]=k4.w;
        }
        for (int i = tid; i < 1024; i += 256) {
            int j = i >> 4, d4 = (i & 15) << 2;
            *(float4*)&Vs[j * 64 + d4] = *(const float4*)&Vb[((size_t)(jbase + j) << 6) + d4];
        }
        if (tid < 64)
            rem[tid] = (mask[b * 2048 + jbase + tid] != 0) ? NEGF : 0.f;
        __syncthreads();

        float s[4][4];
#pragma unroll
        for (int i = 0; i < 4; i++)
#pragma unroll
            for (int j = 0; j < 4; j++) s[i][j] = 0.f;
#pragma unroll 8
        for (int dd = 0; dd < 64; dd++) {
            float4 a = *(const float4*)&Qs[dd * 64 + r0];
            float4 kk = *(const float4*)&Ks[dd * 64 + c0];
            float av[4] = {a.x,a.y,a.z,a.w};
            float kv[4] = {kk.x,kk.y,kk.z,kk.w};
#pragma unroll
            for (int i = 0; i < 4; i++)
#pragma unroll
                for (int j = 0; j < 4; j++)
                    s[i][j] = fmaf(av[i], kv[j], s[i][j]);
        }

#pragma unroll
        for (int i = 0; i < 4; i++) {
            float mx = -INFINITY;
#pragma unroll
            for (int j = 0; j < 4; j++) {
                int c = c0 + j, r = r0 + i;
                float sc = s[i][j] + rem[c];
                int dist = jbase + c - qstart - r;
                if (dist < -128 || dist > 128) sc = -INFINITY;
                s[i][j] = sc;
                mx = fmaxf(mx, sc);
            }
#pragma unroll
            for (int off = 8; off > 0; off >>= 1)
                mx = fmaxf(mx, __shfl_xor_sync(0xffffffffu, mx, off, 16));
            float mnew = fmaxf(mrow[i], mx);
            float corr = __expf(mrow[i] - mnew);
            mrow[i] = mnew;
            float ps = 0.f;
#pragma unroll
            for (int j = 0; j < 4; j++) {
                float p = __expf(s[i][j] - mnew);
                Ps[(r0 + i) * 65 + c0 + j] = p;
                ps += p;
            }
#pragma unroll
            for (int off = 8; off > 0; off >>= 1)
                ps += __shfl_xor_sync(0xffffffffu, ps, off, 16);
            lrow[i] = lrow[i] * corr + ps;
#pragma unroll
            for (int j = 0; j < 4; j++) O[i][j] *= corr;
        }
        __syncthreads();

#pragma unroll 8
        for (int jj = 0; jj < 64; jj++) {
            float4 vv = *(const float4*)&Vs[jj * 64 + c0];
            float pv[4] = {vv.x, vv.y, vv.z, vv.w};
#pragma unroll
            for (int i = 0; i < 4; i++) {
                float p = Ps[(r0 + i) * 65 + jj];
#pragma unroll
                for (int j = 0; j < 4; j++)
                    O[i][j] = fmaf(p, pv[j], O[i][j]);
            }
        }
    }

    const float* bkh = bk + h * 64;
    const float* bvh = bv + h * 64;
    float gp[4] = {0.f, 0.f, 0.f, 0.f};
#pragma unroll
    for (int t = 0; t < 4; t++) {
        int dd = c0 + t;
        float kbv = bkh[dd];
#pragma unroll
        for (int i = 0; i < 4; i++)
            gp[i] += Qs[dd * 64 + r0 + i] * kbv;
    }
#pragma unroll
    for (int i = 0; i < 4; i++) {
#pragma unroll
        for (int off = 8; off > 0; off >>= 1)
            gp[i] += __shfl_xor_sync(0xffffffffu, gp[i], off, 16);
        float g = gp[i];
        float mnew = fmaxf(mrow[i], g);
        float corr = __expf(mrow[i] - mnew);
        float eg = __expf(g - mnew);
        lrow[i] = lrow[i] * corr + eg;
        mrow[i] = mnew;
#pragma unroll
        for (int j = 0; j < 4; j++)
            O[i][j] = O[i][j] * corr + eg * bvh[c0 + j];
    }

#pragma unroll
    for (int i = 0; i < 4; i++) {
        int srow = qstart + r0 + i;
        int mv = mask[b * 2048 + srow];
        float inv = (mv > 0) ? 0.f : (1.f / lrow[i]);
        float4 o;
        o.x = O[i][0]*inv; o.y = O[i][1]*inv; o.z = O[i][2]*inv; o.w = O[i][3]*inv;
        *(float4*)&out[(((size_t)(b * 2048 + srow)) << 10) + (h << 6) + c0] = o;
    }
}

// ---------------------------------------------------------------------------
// y = LN(x + attn) * gamma + beta; also emits bf16 hi/lo of y for MLP1 input
// ---------------------------------------------------------------------------
__global__ __launch_bounds__(256)
void ln_kernel(const float* __restrict__ x, const float* __restrict__ attn,
               const float* __restrict__ gamma, const float* __restrict__ beta,
               float* __restrict__ y, __nv_bfloat16* __restrict__ yhi,
               __nv_bfloat16* __restrict__ ylo)
{
    __shared__ float red[8];
    __shared__ float stat;
    const int row = blockIdx.x, tid = threadIdx.x;
    const int lane = tid & 31, wid = tid >> 5;
    const float* xr = x + ((size_t)row << 10);
    const float* ar = attn + ((size_t)row << 10);
    float v[4];
#pragma unroll
    for (int i = 0; i < 4; i++) {
        int c = tid + (i << 8);
        v[i] = xr[c] + ar[c];
    }
    float s = v[0] + v[1] + v[2] + v[3];
#pragma unroll
    for (int off = 16; off > 0; off >>= 1) s += __shfl_xor_sync(~0u, s, off);
    if (lane == 0) red[wid] = s;
    __syncthreads();
    if (tid == 0) {
        float t = 0.f;
        for (int i = 0; i < 8; i++) t += red[i];
        stat = t * (1.f / 1024.f);
    }
    __syncthreads();
    const float mu = stat;
    float d2 = 0.f;
#pragma unroll
    for (int i = 0; i < 4; i++) { float d = v[i] - mu; d2 += d * d; }
#pragma unroll
    for (int off = 16; off > 0; off >>= 1) d2 += __shfl_xor_sync(~0u, d2, off);
    if (lane == 0) red[wid] = d2;
    __syncthreads();
    if (tid == 0) {
        float t = 0.f;
        for (int i = 0; i < 8; i++) t += red[i];
        stat = rsqrtf(t * (1.f / 1024.f) + 1e-5f);
    }
    __syncthreads();
    const float rs = stat;
    float* yr = y + ((size_t)row << 10);
#pragma unroll
    for (int i = 0; i < 4; i++) {
        int c = tid + (i << 8);
        float val = (v[i] - mu) * rs * gamma[c] + beta[c];
        yr[c] = val;
        __nv_bfloat16 h = __float2bfloat16(val);
        size_t o = ((size_t)row << 10) + c;
        yhi[o] = h;
        ylo[o] = __float2bfloat16(val - __bfloat162float(h));
    }
}

// ---------------------------------------------------------------------------
extern "C" void kernel_launch(void* const* d_in, const int* in_sizes, int n_in,
                              void* d_out, int out_size)
{
    const float* x    = (const float*)d_in[0];
    const int*   mask = (const int*)d_in[1];
    const float* wq   = (const float*)d_in[2];
    const float* bq   = (const float*)d_in[3];
    const float* wk   = (const float*)d_in[4];
    const float* bk   = (const float*)d_in[5];
    const float* wv   = (const float*)d_in[6];
    const float* bv   = (const float*)d_in[7];
    const float* ln_g = (const float*)d_in[14];
    const float* ln_b = (const float*)d_in[15];
    const float* w1   = (const float*)d_in[16];
    const float* b1   = (const float*)d_in[17];
    const float* w2   = (const float*)d_in[18];
    const float* b2   = (const float*)d_in[19];

    float *q, *k, *v, *attn, *y;
    __nv_bfloat16 *xhi, *xlo, *yhi, *ylo, *hhi, *hlo;
    __nv_bfloat16 *wqh, *wql, *wkh, *wkl, *wvh, *wvl, *w1h, *w1l, *w2h, *w2l;
    cudaGetSymbolAddress((void**)&q,    g_q);
    cudaGetSymbolAddress((void**)&k,    g_k);
    cudaGetSymbolAddress((void**)&v,    g_v);
    cudaGetSymbolAddress((void**)&attn, g_attn);
    cudaGetSymbolAddress((void**)&y,    g_y);
    cudaGetSymbolAddress((void**)&xhi,  g_xhi);
    cudaGetSymbolAddress((void**)&xlo,  g_xlo);
    cudaGetSymbolAddress((void**)&yhi,  g_yhi);
    cudaGetSymbolAddress((void**)&ylo,  g_ylo);
    cudaGetSymbolAddress((void**)&hhi,  g_hhi);
    cudaGetSymbolAddress((void**)&hlo,  g_hlo);
    cudaGetSymbolAddress((void**)&wqh,  g_wqt_hi);
    cudaGetSymbolAddress((void**)&wql,  g_wqt_lo);
    cudaGetSymbolAddress((void**)&wkh,  g_wkt_hi);
    cudaGetSymbolAddress((void**)&wkl,  g_wkt_lo);
    cudaGetSymbolAddress((void**)&wvh,  g_wvt_hi);
    cudaGetSymbolAddress((void**)&wvl,  g_wvt_lo);
    cudaGetSymbolAddress((void**)&w1h,  g_w1t_hi);
    cudaGetSymbolAddress((void**)&w1l,  g_w1t_lo);
    cudaGetSymbolAddress((void**)&w2h,  g_w2t_hi);
    cudaGetSymbolAddress((void**)&w2l,  g_w2t_lo);

    const int ATT_SMEM = (64*64*3 + 64*65 + 64) * 4;  // 66048 B
    const int G_SMEM = 2 * BUF_B;                     // 147456 B
    cudaFuncSetAttribute(attn_kernel,
                         cudaFuncAttributeMaxDynamicSharedMemorySize, ATT_SMEM);
    cudaFuncSetAttribute(mma_gemm<0>,
                         cudaFuncAttributeMaxDynamicSharedMemorySize, G_SMEM);
    cudaFuncSetAttribute(mma_gemm<1>,
                         cudaFuncAttributeMaxDynamicSharedMemorySize, G_SMEM);
    cudaFuncSetAttribute(mma_gemm<2>,
                         cudaFuncAttributeMaxDynamicSharedMemorySize, G_SMEM);

    // input / weight conversion
    split_kernel<<<4096, 256>>>((const float4*)x, (__nv_bfloat162*)xhi,
                                (__nv_bfloat162*)xlo, 1048576);
    tsplit_kernel<<<dim3(32, 32),  256>>>(wq, wqh, wql, 1024, 1024);
    tsplit_kernel<<<dim3(32, 32),  256>>>(wk, wkh, wkl, 1024, 1024);
    tsplit_kernel<<<dim3(32, 32),  256>>>(wv, wvh, wvl, 1024, 1024);
    tsplit_kernel<<<dim3(128, 32), 256>>>(w1, w1h, w1l, 1024, 4096);
    tsplit_kernel<<<dim3(32, 128), 256>>>(w2, w2h, w2l, 4096, 1024);

    // QKV projections (HMMA)
    mma_gemm<0><<<dim3(8, 32), 256, G_SMEM>>>(xhi, xlo, wqh, wql, bq, nullptr,
                                              q, nullptr, nullptr, 4096, 1024, 1024, 0.125f);
    mma_gemm<0><<<dim3(8, 32), 256, G_SMEM>>>(xhi, xlo, wkh, wkl, bk, nullptr,
                                              k, nullptr, nullptr, 4096, 1024, 1024, 1.0f);
    mma_gemm<0><<<dim3(8, 32), 256, G_SMEM>>>(xhi, xlo, wvh, wvl, bv, nullptr,
                                              v, nullptr, nullptr, 4096, 1024, 1024, 1.0f);
    // banded attention + global key
    attn_kernel<<<dim3(32, 16, 2), 256, ATT_SMEM>>>(q, k, v, mask, bk, bv, attn);
    // residual add + layernorm (emits fp32 + bf16 hi/lo)
    ln_kernel<<<4096, 256>>>(x, attn, ln_g, ln_b, y, yhi, ylo);
    // MLP
    mma_gemm<1><<<dim3(32, 32), 256, G_SMEM>>>(yhi, ylo, w1h, w1l, b1, nullptr,
                                               nullptr, hhi, hlo, 4096, 4096, 1024, 1.0f);
    mma_gemm<2><<<dim3(8, 32), 256, G_SMEM>>>(hhi, hlo, w2h, w2l, b2, y,
                                              (float*)d_out, nullptr, nullptr, 4096, 1024, 4096, 1.0f);
}

// round 5
// speedup vs baseline: 2.3425x; 1.3699x over previous
#include <cuda_runtime.h>
#include <cuda_fp16.h>
#include <math.h>
#include <stdint.h>

// ---------------------------------------------------------------------------
// HFLongFormerSelfAttentionBlock on GB300 (sm_103 base PTX target -> mma.sync)
// R4: GEMMs use fp16 2-term weight-split (w*1024 = whi + wlo, activations
//     single fp16): acc = xh@whi + xh@wlo, epilogue * 1/1024.  -33% MMAs vs R3.
// ---------------------------------------------------------------------------

#define NEGF (-3.4028234663852886e38f)
#define INV_WS (1.0f / 1024.0f)

// ---------------- scratch (device globals; no allocation allowed) ----------
__device__ float g_q[4194304];     // (B,NH,S0,HD)
__device__ float g_k[4194304];
__device__ float g_v[4194304];
__device__ float g_attn[4194304];  // (B*S0, H)
__device__ float g_y[4194304];     // LN output fp32
__device__ __half g_xh[4194304];
__device__ __half g_yh[4194304];
__device__ __half g_hh[16777216];
__device__ __half g_wqt_hi[1048576], g_wqt_lo[1048576];
__device__ __half g_wkt_hi[1048576], g_wkt_lo[1048576];
__device__ __half g_wvt_hi[1048576], g_wvt_lo[1048576];
__device__ __half g_w1t_hi[4194304], g_w1t_lo[4194304];
__device__ __half g_w2t_hi[4194304], g_w2t_lo[4194304];

// ---------------- PTX helpers ----------------------------------------------
__device__ __forceinline__ uint32_t smem_u32(const void* p) {
    uint32_t a;
    asm("{ .reg .u64 t; cvta.to.shared.u64 t, %1; cvt.u32.u64 %0, t; }"
        : "=r"(a) : "l"(p));
    return a;
}
__device__ __forceinline__ void cp_async16(uint32_t saddr, const void* gptr) {
    asm volatile("cp.async.ca.shared.global [%0], [%1], 16;"
                 :: "r"(saddr), "l"(gptr));
}
__device__ __forceinline__ void cp_commit() {
    asm volatile("cp.async.commit_group;");
}
template<int N>
__device__ __forceinline__ void cp_wait() {
    asm volatile("cp.async.wait_group %0;" :: "n"(N));
}
__device__ __forceinline__ void ldsm_x4(uint32_t& r0, uint32_t& r1,
                                        uint32_t& r2, uint32_t& r3, uint32_t a) {
    asm volatile("ldmatrix.sync.aligned.m8n8.x4.shared.b16 {%0,%1,%2,%3}, [%4];"
                 : "=r"(r0), "=r"(r1), "=r"(r2), "=r"(r3) : "r"(a));
}
__device__ __forceinline__ void mma_f16(float* c, const uint32_t* a,
                                        uint32_t b0, uint32_t b1) {
    asm volatile(
        "mma.sync.aligned.m16n8k16.row.col.f32.f16.f16.f32 "
        "{%0,%1,%2,%3}, {%4,%5,%6,%7}, {%8,%9}, {%0,%1,%2,%3};"
        : "+f"(c[0]), "+f"(c[1]), "+f"(c[2]), "+f"(c[3])
        : "r"(a[0]), "r"(a[1]), "r"(a[2]), "r"(a[3]), "r"(b0), "r"(b1));
}

// ---------------------------------------------------------------------------
// split: fp32 -> fp16 elementwise (vectorized by 4)
// ---------------------------------------------------------------------------
__global__ __launch_bounds__(256)
void split_kernel(const float4* __restrict__ in, __half2* __restrict__ hi, int n4)
{
    int i = blockIdx.x * 256 + threadIdx.x;
    if (i >= n4) return;
    float4 v = in[i];
    hi[2*i]   = __floats2half2_rn(v.x, v.y);
    hi[2*i+1] = __floats2half2_rn(v.z, v.w);
}

// ---------------------------------------------------------------------------
// transpose-split: W[K,N] fp32 -> Thi/Tlo[N,K] fp16 of (w*1024)
// ---------------------------------------------------------------------------
__global__ __launch_bounds__(256)
void tsplit_kernel(const float* __restrict__ W, __half* __restrict__ Thi,
                   __half* __restrict__ Tlo, int K, int N)
{
    __shared__ float ts[32][33];
    const int k0 = blockIdx.y << 5, n0 = blockIdx.x << 5;
    for (int i = threadIdx.x; i < 1024; i += 256) {
        int r = i >> 5, c = i & 31;
        ts[r][c] = W[(size_t)(k0 + r) * N + n0 + c];
    }
    __syncthreads();
    for (int i = threadIdx.x; i < 1024; i += 256) {
        int r = i >> 5, c = i & 31;   // r = n index, c = k index
        float v = ts[c][r] * 1024.0f;
        __half h = __float2half(v);
        size_t o = (size_t)(n0 + r) * K + k0 + c;
        Thi[o] = h;
        Tlo[o] = __float2half(v - __half2float(h));
    }
}

// ---------------------------------------------------------------------------
// HMMA fp16 2-term GEMM: out = epi((Ah[M,K] @ (Bhi+Blo)[N,K]^T) * 1/1024 ...)
// CTA 128x128, BK=64, 256 threads (8 warps 2x4, warp tile 64x32),
// smem row stride 72 fp16 (conflict-free ldmatrix), 3-stage cp.async pipe.
// EPI 0: (acc/1024 + bias)*scale -> (B,NH,S,HD) remap (QKV)
// EPI 1: gelu(acc/1024 + bias) -> fp16 (MLP hidden)
// EPI 2: acc/1024 + bias + res -> fp32 (final output)
// ---------------------------------------------------------------------------
#define SA_STRIDE 72
#define TILE_B    18432   // 128*72*2 bytes per array
#define STAGE_B   55296   // 3 arrays (A, Bhi, Blo)

template<int EPI>
__global__ __launch_bounds__(256)
void mma_gemm(const __half* __restrict__ Ah,
              const __half* __restrict__ Bhi, const __half* __restrict__ Blo,
              const float* __restrict__ bias, const float* __restrict__ res,
              float* __restrict__ Cf, __half* __restrict__ Ch,
              int M, int N, int K, float scale)
{
    extern __shared__ char smem[];
    const uint32_t sb = smem_u32(smem);
    const int tid = threadIdx.x, wid = tid >> 5, lane = tid & 31;
    const int m0 = blockIdx.y << 7, n0 = blockIdx.x << 7;
    const int wm = (wid >> 2) << 6;       // 0 or 64
    const int wn = (wid & 3) << 5;        // 0,32,64,96

    // ldmatrix lane addressing (element offsets)
    const int a_row = lane & 15, a_kof = (lane >> 4) << 3;
    const int b_row = ((lane >> 4) << 3) + (lane & 7), b_kof = ((lane >> 3) & 1) << 3;

    // global->smem copy mapping: row = tid>>1, chunks of 8 fp16
    const int c_row = tid >> 1, c_col = (tid & 1) << 5;

    float acc[4][4][4];
#pragma unroll
    for (int mt = 0; mt < 4; mt++)
#pragma unroll
        for (int nt = 0; nt < 4; nt++)
#pragma unroll
            for (int r = 0; r < 4; r++) acc[mt][nt][r] = 0.f;

    const int nk = K >> 6;

    auto load_tile = [&](int buf, int kt) {
        const uint32_t sbase = sb + buf * STAGE_B;
        const size_t gka = (size_t)(m0 + c_row) * K + ((size_t)kt << 6) + c_col;
        const size_t gkb = (size_t)(n0 + c_row) * K + ((size_t)kt << 6) + c_col;
        const uint32_t soff = (c_row * SA_STRIDE + c_col) * 2;
#pragma unroll
        for (int j = 0; j < 4; j++) {
            cp_async16(sbase + soff + j * 16,              Ah  + gka + j * 8);
            cp_async16(sbase + TILE_B   + soff + j * 16,   Bhi + gkb + j * 8);
            cp_async16(sbase + 2*TILE_B + soff + j * 16,   Blo + gkb + j * 8);
        }
        cp_commit();
    };

    load_tile(0, 0);
    load_tile(1, 1);

    for (int kt = 0; kt < nk; kt++) {
        const int buf = kt % 3;
        if (kt + 2 < nk) { load_tile((kt + 2) % 3, kt + 2); cp_wait<2>(); }
        else if (kt + 1 < nk) { cp_wait<1>(); }
        else { cp_wait<0>(); }
        __syncthreads();

        const uint32_t sA   = sb + buf * STAGE_B;
        const uint32_t sBhi = sA + TILE_B;
        const uint32_t sBlo = sA + 2 * TILE_B;

#pragma unroll
        for (int ks = 0; ks < 4; ks++) {
            const int k0 = ks << 4;
            uint32_t ah[4][4];
#pragma unroll
            for (int mt = 0; mt < 4; mt++) {
                const uint32_t off =
                    ((wm + (mt << 4) + a_row) * SA_STRIDE + k0 + a_kof) * 2;
                ldsm_x4(ah[mt][0], ah[mt][1], ah[mt][2], ah[mt][3], sA + off);
            }
            uint32_t bh[4][2], bl[4][2];
#pragma unroll
            for (int nt2 = 0; nt2 < 2; nt2++) {
                const uint32_t off =
                    ((wn + (nt2 << 4) + b_row) * SA_STRIDE + k0 + b_kof) * 2;
                uint32_t r0, r1, r2, r3;
                ldsm_x4(r0, r1, r2, r3, sBhi + off);
                bh[nt2*2][0] = r0; bh[nt2*2][1] = r1;
                bh[nt2*2+1][0] = r2; bh[nt2*2+1][1] = r3;
                ldsm_x4(r0, r1, r2, r3, sBlo + off);
                bl[nt2*2][0] = r0; bl[nt2*2][1] = r1;
                bl[nt2*2+1][0] = r2; bl[nt2*2+1][1] = r3;
            }
#pragma unroll
            for (int mt = 0; mt < 4; mt++)
#pragma unroll
                for (int nt = 0; nt < 4; nt++) {
                    mma_f16(acc[mt][nt], ah[mt], bh[nt][0], bh[nt][1]);
                    mma_f16(acc[mt][nt], ah[mt], bl[nt][0], bl[nt][1]);
                }
        }
        __syncthreads();
    }

    // ---- epilogue ----
    const int mrow_b = m0 + wm + (lane >> 2);
    const int ncol_b = n0 + wn + ((lane & 3) << 1);
#pragma unroll
    for (int mt = 0; mt < 4; mt++) {
#pragma unroll
        for (int half_ = 0; half_ < 2; half_++) {
            const int m = mrow_b + (mt << 4) + (half_ << 3);
#pragma unroll
            for (int nt = 0; nt < 4; nt++) {
                const int ncol = ncol_b + (nt << 3);
                const float b0 = bias[ncol], b1 = bias[ncol + 1];
                float o0 = acc[mt][nt][half_*2+0] * INV_WS + b0;
                float o1 = acc[mt][nt][half_*2+1] * INV_WS + b1;
                if (EPI == 0) {
                    o0 *= scale; o1 *= scale;
                    const int bi = m >> 11, ss = m & 2047;
                    const int hh = ncol >> 6, dd = ncol & 63;
                    float2* p = (float2*)&Cf[(((size_t)((bi*16 + hh)*2048 + ss)) << 6) + dd];
                    *p = make_float2(o0, o1);
                } else if (EPI == 1) {
                    const float c_ = 0.70710678118654752f;
                    float g0 = 0.5f * o0 * (1.f + erff(o0 * c_));
                    float g1 = 0.5f * o1 * (1.f + erff(o1 * c_));
                    *(__half2*)(Ch + (size_t)m * N + ncol) = __floats2half2_rn(g0, g1);
                } else {
                    const float2 r4 = *(const float2*)&res[(size_t)m * N + ncol];
                    *(float2*)&Cf[(size_t)m * N + ncol] =
                        make_float2(o0 + r4.x, o1 + r4.y);
                }
            }
        }
    }
}

// ---------------------------------------------------------------------------
// Banded attention with online softmax + global-key epilogue (R1, unchanged)
// ---------------------------------------------------------------------------
__global__ __launch_bounds__(256)
void attn_kernel(const float* __restrict__ Q, const float* __restrict__ Kt,
                 const float* __restrict__ Vt, const int* __restrict__ mask,
                 const float* __restrict__ bk, const float* __restrict__ bv,
                 float* __restrict__ out)
{
    extern __shared__ float sm[];
    float* Qs = sm;                 // 64x64  [d][r]
    float* Ks = sm + 4096;          // 64x64  [d][c]
    float* Vs = sm + 8192;          // 64x64  [j][d]
    float* Ps = sm + 12288;         // 64x65  [r][c]
    float* rem = sm + 12288 + 64*65;

    const int qb = blockIdx.x, h = blockIdx.y, b = blockIdx.z;
    const int qstart = qb << 6;
    const int tid = threadIdx.x, tx = tid & 15, ty = tid >> 4;
    const size_t bh = (size_t)(b * 16 + h) * 2048 * 64;
    const float* Qb = Q + bh;
    const float* Kb = Kt + bh;
    const float* Vb = Vt + bh;
    const int r0 = ty << 2, c0 = tx << 2;

    for (int i = tid; i < 1024; i += 256) {
        int r = i & 63, d4 = (i >> 6) << 2;
        float4 q4 = *(const float4*)&Qb[((size_t)(qstart + r) << 6) + d4];
        Qs[(d4+0)*64+r]=q4.x; Qs[(d4+1)*64+r]=q4.y;
        Qs[(d4+2)*64+r]=q4.z; Qs[(d4+3)*64+r]=q4.w;
    }

    float O[4][4];
    float mrow[4], lrow[4];
#pragma unroll
    for (int i = 0; i < 4; i++) {
        mrow[i] = -INFINITY; lrow[i] = 0.f;
#pragma unroll
        for (int j = 0; j < 4; j++) O[i][j] = 0.f;
    }

    for (int ch = 0; ch < 5; ch++) {
        const int jbase = qstart - 128 + (ch << 6);
        if (jbase < 0 || jbase >= 2048) continue;
        __syncthreads();
        for (int i = tid; i < 1024; i += 256) {
            int c = i & 63, d4 = (i >> 6) << 2;
            float4 k4 = *(const float4*)&Kb[((size_t)(jbase + c) << 6) + d4];
            Ks[(d4+0)*64+c]=k4.x; Ks[(d4+1)*64+c]=k4.y;
            Ks[(d4+2)*64+c]=k4.z; Ks[(d4+3)*64+c]=k4.w;
        }
        for (int i = tid; i < 1024; i += 256) {
            int j = i >> 4, d4 = (i & 15) << 2;
            *(float4*)&Vs[j * 64 + d4] = *(const float4*)&Vb[((size_t)(jbase + j) << 6) + d4];
        }
        if (tid < 64)
            rem[tid] = (mask[b * 2048 + jbase + tid] != 0) ? NEGF : 0.f;
        __syncthreads();

        float s[4][4];
#pragma unroll
        for (int i = 0; i < 4; i++)
#pragma unroll
            for (int j = 0; j < 4; j++) s[i][j] = 0.f;
#pragma unroll 8
        for (int dd = 0; dd < 64; dd++) {
            float4 a = *(const float4*)&Qs[dd * 64 + r0];
            float4 kk = *(const float4*)&Ks[dd * 64 + c0];
            float av[4] = {a.x,a.y,a.z,a.w};
            float kv[4] = {kk.x,kk.y,kk.z,kk.w};
#pragma unroll
            for (int i = 0; i < 4; i++)
#pragma unroll
                for (int j = 0; j < 4; j++)
                    s[i][j] = fmaf(av[i], kv[j], s[i][j]);
        }

#pragma unroll
        for (int i = 0; i < 4; i++) {
            float mx = -INFINITY;
#pragma unroll
            for (int j = 0; j < 4; j++) {
                int c = c0 + j, r = r0 + i;
                float sc = s[i][j] + rem[c];
                int dist = jbase + c - qstart - r;
                if (dist < -128 || dist > 128) sc = -INFINITY;
                s[i][j] = sc;
                mx = fmaxf(mx, sc);
            }
#pragma unroll
            for (int off = 8; off > 0; off >>= 1)
                mx = fmaxf(mx, __shfl_xor_sync(0xffffffffu, mx, off, 16));
            float mnew = fmaxf(mrow[i], mx);
            float corr = __expf(mrow[i] - mnew);
            mrow[i] = mnew;
            float ps = 0.f;
#pragma unroll
            for (int j = 0; j < 4; j++) {
                float p = __expf(s[i][j] - mnew);
                Ps[(r0 + i) * 65 + c0 + j] = p;
                ps += p;
            }
#pragma unroll
            for (int off = 8; off > 0; off >>= 1)
                ps += __shfl_xor_sync(0xffffffffu, ps, off, 16);
            lrow[i] = lrow[i] * corr + ps;
#pragma unroll
            for (int j = 0; j < 4; j++) O[i][j] *= corr;
        }
        __syncthreads();

#pragma unroll 8
        for (int jj = 0; jj < 64; jj++) {
            float4 vv = *(const float4*)&Vs[jj * 64 + c0];
            float pv[4] = {vv.x, vv.y, vv.z, vv.w};
#pragma unroll
            for (int i = 0; i < 4; i++) {
                float p = Ps[(r0 + i) * 65 + jj];
#pragma unroll
                for (int j = 0; j < 4; j++)
                    O[i][j] = fmaf(p, pv[j], O[i][j]);
            }
        }
    }

    const float* bkh = bk + h * 64;
    const float* bvh = bv + h * 64;
    float gp[4] = {0.f, 0.f, 0.f, 0.f};
#pragma unroll
    for (int t = 0; t < 4; t++) {
        int dd = c0 + t;
        float kbv = bkh[dd];
#pragma unroll
        for (int i = 0; i < 4; i++)
            gp[i] += Qs[dd * 64 + r0 + i] * kbv;
    }
#pragma unroll
    for (int i = 0; i < 4; i++) {
#pragma unroll
        for (int off = 8; off > 0; off >>= 1)
            gp[i] += __shfl_xor_sync(0xffffffffu, gp[i], off, 16);
        float g = gp[i];
        float mnew = fmaxf(mrow[i], g);
        float corr = __expf(mrow[i] - mnew);
        float eg = __expf(g - mnew);
        lrow[i] = lrow[i] * corr + eg;
        mrow[i] = mnew;
#pragma unroll
        for (int j = 0; j < 4; j++)
            O[i][j] = O[i][j] * corr + eg * bvh[c0 + j];
    }

#pragma unroll
    for (int i = 0; i < 4; i++) {
        int srow = qstart + r0 + i;
        int mv = mask[b * 2048 + srow];
        float inv = (mv > 0) ? 0.f : (1.f / lrow[i]);
        float4 o;
        o.x = O[i][0]*inv; o.y = O[i][1]*inv; o.z = O[i][2]*inv; o.w = O[i][3]*inv;
        *(float4*)&out[(((size_t)(b * 2048 + srow)) << 10) + (h << 6) + c0] = o;
    }
}

// ---------------------------------------------------------------------------
// y = LN(x + attn) * gamma + beta; also emits fp16 y for MLP1 input
// ---------------------------------------------------------------------------
__global__ __launch_bounds__(256)
void ln_kernel(const float* __restrict__ x, const float* __restrict__ attn,
               const float* __restrict__ gamma, const float* __restrict__ beta,
               float* __restrict__ y, __half* __restrict__ yh)
{
    __shared__ float red[8];
    __shared__ float stat;
    const int row = blockIdx.x, tid = threadIdx.x;
    const int lane = tid & 31, wid = tid >> 5;
    const float* xr = x + ((size_t)row << 10);
    const float* ar = attn + ((size_t)row << 10);
    float v[4];
#pragma unroll
    for (int i = 0; i < 4; i++) {
        int c = tid + (i << 8);
        v[i] = xr[c] + ar[c];
    }
    float s = v[0] + v[1] + v[2] + v[3];
#pragma unroll
    for (int off = 16; off > 0; off >>= 1) s += __shfl_xor_sync(~0u, s, off);
    if (lane == 0) red[wid] = s;
    __syncthreads();
    if (tid == 0) {
        float t = 0.f;
        for (int i = 0; i < 8; i++) t += red[i];
        stat = t * (1.f / 1024.f);
    }
    __syncthreads();
    const float mu = stat;
    float d2 = 0.f;
#pragma unroll
    for (int i = 0; i < 4; i++) { float d = v[i] - mu; d2 += d * d; }
#pragma unroll
    for (int off = 16; off > 0; off >>= 1) d2 += __shfl_xor_sync(~0u, d2, off);
    if (lane == 0) red[wid] = d2;
    __syncthreads();
    if (tid == 0) {
        float t = 0.f;
        for (int i = 0; i < 8; i++) t += red[i];
        stat = rsqrtf(t * (1.f / 1024.f) + 1e-5f);
    }
    __syncthreads();
    const float rs = stat;
    float* yr = y + ((size_t)row << 10);
#pragma unroll
    for (int i = 0; i < 4; i++) {
        int c = tid + (i << 8);
        float val = (v[i] - mu) * rs * gamma[c] + beta[c];
        yr[c] = val;
        yh[((size_t)row << 10) + c] = __float2half(val);
    }
}

// ---------------------------------------------------------------------------
extern "C" void kernel_launch(void* const* d_in, const int* in_sizes, int n_in,
                              void* d_out, int out_size)
{
    const float* x    = (const float*)d_in[0];
    const int*   mask = (const int*)d_in[1];
    const float* wq   = (const float*)d_in[2];
    const float* bq   = (const float*)d_in[3];
    const float* wk   = (const float*)d_in[4];
    const float* bk   = (const float*)d_in[5];
    const float* wv   = (const float*)d_in[6];
    const float* bv   = (const float*)d_in[7];
    const float* ln_g = (const float*)d_in[14];
    const float* ln_b = (const float*)d_in[15];
    const float* w1   = (const float*)d_in[16];
    const float* b1   = (const float*)d_in[17];
    const float* w2   = (const float*)d_in[18];
    const float* b2   = (const float*)d_in[19];

    float *q, *k, *v, *attn, *y;
    __half *xh, *yh, *hh;
    __half *wqh, *wql, *wkh, *wkl, *wvh, *wvl, *w1h, *w1l, *w2h, *w2l;
    cudaGetSymbolAddress((void**)&q,    g_q);
    cudaGetSymbolAddress((void**)&k,    g_k);
    cudaGetSymbolAddress((void**)&v,    g_v);
    cudaGetSymbolAddress((void**)&attn, g_attn);
    cudaGetSymbolAddress((void**)&y,    g_y);
    cudaGetSymbolAddress((void**)&xh,   g_xh);
    cudaGetSymbolAddress((void**)&yh,   g_yh);
    cudaGetSymbolAddress((void**)&hh,   g_hh);
    cudaGetSymbolAddress((void**)&wqh,  g_wqt_hi);
    cudaGetSymbolAddress((void**)&wql,  g_wqt_lo);
    cudaGetSymbolAddress((void**)&wkh,  g_wkt_hi);
    cudaGetSymbolAddress((void**)&wkl,  g_wkt_lo);
    cudaGetSymbolAddress((void**)&wvh,  g_wvt_hi);
    cudaGetSymbolAddress((void**)&wvl,  g_wvt_lo);
    cudaGetSymbolAddress((void**)&w1h,  g_w1t_hi);
    cudaGetSymbolAddress((void**)&w1l,  g_w1t_lo);
    cudaGetSymbolAddress((void**)&w2h,  g_w2t_hi);
    cudaGetSymbolAddress((void**)&w2l,  g_w2t_lo);

    const int ATT_SMEM = (64*64*3 + 64*65 + 64) * 4;  // 66048 B
    const int G_SMEM = 3 * STAGE_B;                   // 165888 B
    cudaFuncSetAttribute(attn_kernel,
                         cudaFuncAttributeMaxDynamicSharedMemorySize, ATT_SMEM);
    cudaFuncSetAttribute(mma_gemm<0>,
                         cudaFuncAttributeMaxDynamicSharedMemorySize, G_SMEM);
    cudaFuncSetAttribute(mma_gemm<1>,
                         cudaFuncAttributeMaxDynamicSharedMemorySize, G_SMEM);
    cudaFuncSetAttribute(mma_gemm<2>,
                         cudaFuncAttributeMaxDynamicSharedMemorySize, G_SMEM);

    // input / weight conversion
    split_kernel<<<4096, 256>>>((const float4*)x, (__half2*)xh, 1048576);
    tsplit_kernel<<<dim3(32, 32),  256>>>(wq, wqh, wql, 1024, 1024);
    tsplit_kernel<<<dim3(32, 32),  256>>>(wk, wkh, wkl, 1024, 1024);
    tsplit_kernel<<<dim3(32, 32),  256>>>(wv, wvh, wvl, 1024, 1024);
    tsplit_kernel<<<dim3(128, 32), 256>>>(w1, w1h, w1l, 1024, 4096);
    tsplit_kernel<<<dim3(32, 128), 256>>>(w2, w2h, w2l, 4096, 1024);

    // QKV projections (HMMA)
    mma_gemm<0><<<dim3(8, 32), 256, G_SMEM>>>(xh, wqh, wql, bq, nullptr,
                                              q, nullptr, 4096, 1024, 1024, 0.125f);
    mma_gemm<0><<<dim3(8, 32), 256, G_SMEM>>>(xh, wkh, wkl, bk, nullptr,
                                              k, nullptr, 4096, 1024, 1024, 1.0f);
    mma_gemm<0><<<dim3(8, 32), 256, G_SMEM>>>(xh, wvh, wvl, bv, nullptr,
                                              v, nullptr, 4096, 1024, 1024, 1.0f);
    // banded attention + global key
    attn_kernel<<<dim3(32, 16, 2), 256, ATT_SMEM>>>(q, k, v, mask, bk, bv, attn);
    // residual add + layernorm (emits fp32 + fp16)
    ln_kernel<<<4096, 256>>>(x, attn, ln_g, ln_b, y, yh);
    // MLP
    mma_gemm<1><<<dim3(32, 32), 256, G_SMEM>>>(yh, w1h, w1l, b1, nullptr,
                                               nullptr, hh, 4096, 4096, 1024, 1.0f);
    mma_gemm<2><<<dim3(8, 32), 256, G_SMEM>>>(hh, w2h, w2l, b2, y,
                                              (float*)d_out, nullptr, 4096, 1024, 4096, 1.0f);
}